// round 2
// baseline (speedup 1.0000x reference)
#include <cuda_runtime.h>

#define BB 16
#define CC_FEAT 96
#define HH 128
#define WW 128
#define HWSZ (HH*WW)

// ---- scratch (device globals; no allocation allowed) ----
__device__ float g_flow [BB*2  *HWSZ];
__device__ float g_feat2[BB*CC_FEAT*HWSZ];
__device__ float g_corr [BB*49 *HWSZ];
__device__ float g_x1   [BB*128*HWSZ];
__device__ float g_x2   [BB*64 *HWSZ];
__device__ float g_x3   [BB*32 *HWSZ];

// ---------------------------------------------------------------------------
// 1) upflow: depthwise transposed conv, stride 2, 4x4 (flipped), pad 2
// ---------------------------------------------------------------------------
__global__ void k_upflow(const float* __restrict__ tf, const float* __restrict__ wu) {
    int idx = blockIdx.x * blockDim.x + threadIdx.x;      // 512*1024 = 524288 exact
    int ox = idx & 127, oy = (idx >> 7) & 127, c = (idx >> 14) & 1, b = idx >> 15;
    float acc = 0.f;
#pragma unroll
    for (int ky = 0; ky < 4; ky++) {
        int iy = oy + ky - 2;
        if (iy < 0 || iy > 126 || (iy & 1)) continue;
        iy >>= 1;
#pragma unroll
        for (int kx = 0; kx < 4; kx++) {
            int ix = ox + kx - 2;
            if (ix < 0 || ix > 126 || (ix & 1)) continue;
            ix >>= 1;
            acc += wu[c*16 + (3-ky)*4 + (3-kx)] * tf[((b*2 + c)*64 + iy)*64 + ix];
        }
    }
    g_flow[idx] = acc;
}

// ---------------------------------------------------------------------------
// 2) backward warp of featuresSecond by flow*2.5 (bilinear, zero pad, mask)
// ---------------------------------------------------------------------------
__global__ void k_warp(const float* __restrict__ feat) {
    int x = threadIdx.x;        // 128
    int y = blockIdx.x;         // 128
    int b = blockIdx.y;         // 16
    int base = b*2*HWSZ + y*WW + x;
    float fx = (float)x + 2.5f * g_flow[base];
    float fy = (float)y + 2.5f * g_flow[base + HWSZ];
    float x0f = floorf(fx), y0f = floorf(fy);
    float wx1 = fx - x0f, wx0 = 1.f - wx1;
    float wy1 = fy - y0f, wy0 = 1.f - wy1;
    int x0 = (int)x0f, y0 = (int)y0f;
    int x1 = x0 + 1,  y1 = y0 + 1;
    bool vx0 = (x0 >= 0) & (x0 < WW), vx1 = (x1 >= 0) & (x1 < WW);
    bool vy0 = (y0 >= 0) & (y0 < HH), vy1 = (y1 >= 0) & (y1 < HH);
    float wa = wx0*wy0, wb = wx1*wy0, wc = wx0*wy1, wd = wx1*wy1;
    float m = wa*(float)(vx0&&vy0) + wb*(float)(vx1&&vy0)
            + wc*(float)(vx0&&vy1) + wd*(float)(vx1&&vy1);
    float mask = (m > 0.999f) ? 1.f : 0.f;
    float ea = (vx0&&vy0) ? wa*mask : 0.f;
    float eb = (vx1&&vy0) ? wb*mask : 0.f;
    float ec = (vx0&&vy1) ? wc*mask : 0.f;
    float ed = (vx1&&vy1) ? wd*mask : 0.f;
    int xa = min(max(x0,0),WW-1), xb = min(max(x1,0),WW-1);
    int ya = min(max(y0,0),HH-1), yb = min(max(y1,0),HH-1);
    const float* fp = feat + (size_t)b*CC_FEAT*HWSZ;
    int oa = ya*WW+xa, ob = ya*WW+xb, oc = yb*WW+xa, od = yb*WW+xb;
    float* outp = g_feat2 + (size_t)b*CC_FEAT*HWSZ + y*WW + x;
#pragma unroll 4
    for (int c = 0; c < CC_FEAT; c++) {
        float v = ea*fp[oa] + eb*fp[ob] + ec*fp[oc] + ed*fp[od];
        *outp = v;
        fp += HWSZ; outp += HWSZ;
    }
}

// ---------------------------------------------------------------------------
// 3) correlation (7x7, mean over 96 ch) + leaky relu -> g_corr (B,49,H,W)
// ---------------------------------------------------------------------------
__global__ void k_corr(const float* __restrict__ first) {
    const int tx = threadIdx.x, ty = threadIdx.y;
    const int x0 = blockIdx.x*32, y0 = blockIdx.y*8, b = blockIdx.z;
    __shared__ float s_f[4][8][32];
    __shared__ float s_p[4][14][40];   // 38 used, padded
    float acc[49];
#pragma unroll
    for (int i = 0; i < 49; i++) acc[i] = 0.f;
    const int tid = ty*32 + tx;

    for (int c0 = 0; c0 < CC_FEAT; c0 += 4) {
#pragma unroll
        for (int cc = 0; cc < 4; cc++)
            s_f[cc][ty][tx] = first[((b*CC_FEAT + c0+cc)*HH + y0+ty)*WW + x0+tx];
        for (int i = tid; i < 4*14*38; i += 256) {
            int cc  = i / (14*38);
            int r   = (i / 38) % 14;
            int col = i % 38;
            int gy = y0 + r - 3, gx = x0 + col - 3;
            float v = 0.f;
            if (gy >= 0 && gy < HH && gx >= 0 && gx < WW)
                v = g_feat2[((b*CC_FEAT + c0+cc)*HH + gy)*WW + gx];
            s_p[cc][r][col] = v;
        }
        __syncthreads();
#pragma unroll
        for (int cc = 0; cc < 4; cc++) {
            float f = s_f[cc][ty][tx];
#pragma unroll
            for (int dy = 0; dy < 7; dy++)
#pragma unroll
                for (int dx = 0; dx < 7; dx++)
                    acc[dy*7+dx] += f * s_p[cc][ty+dy][tx+dx];
        }
        __syncthreads();
    }
    const float inv = 1.f/96.f;
#pragma unroll
    for (int d = 0; d < 49; d++) {
        float v = acc[d]*inv;
        v = (v >= 0.f) ? v : 0.1f*v;
        g_corr[((b*49 + d)*HH + y0+ty)*WW + x0+tx] = v;
    }
}

// ---------------------------------------------------------------------------
// 4) 3x3 conv, pad 1, + bias + leaky relu. block (32,8), tile 32x32 spatial,
//    8 couts/block; each thread: 4 vertical pixels x 8 couts = 32 accums.
// ---------------------------------------------------------------------------
template<int CIN, int COUT, bool RELU>
__device__ __forceinline__ void conv3_body(const float* __restrict__ in,
                                           const float* __restrict__ wt,
                                           const float* __restrict__ bias,
                                           float* __restrict__ out) {
    const int tx = threadIdx.x, ty = threadIdx.y;
    const int x0 = blockIdx.x*32, y0 = blockIdx.y*32;
    const int ng = COUT/8;
    const int b  = blockIdx.z / ng;
    const int co0 = (blockIdx.z % ng)*8;
    __shared__ float s_in[4][34][34];
    __shared__ float s_w[8][4][9];
    float acc[4][8];
#pragma unroll
    for (int p = 0; p < 4; p++)
#pragma unroll
        for (int co = 0; co < 8; co++) acc[p][co] = 0.f;
    const int tid = ty*32 + tx;

    for (int c0 = 0; c0 < CIN; c0 += 4) {
        for (int i = tid; i < 8*4*9; i += 256) {
            int co = i/36, r = i%36, ci = r/9, k = r%9;
            float v = 0.f;
            if (c0+ci < CIN) v = wt[((co0+co)*CIN + c0+ci)*9 + k];
            s_w[co][ci][k] = v;
        }
        for (int i = tid; i < 4*34*34; i += 256) {
            int cc = i/(34*34), r = (i/34)%34, col = i%34;
            int gy = y0 + r - 1, gx = x0 + col - 1;
            float v = 0.f;
            if ((c0+cc) < CIN && gy >= 0 && gy < HH && gx >= 0 && gx < WW)
                v = in[((b*CIN + c0+cc)*HH + gy)*WW + gx];
            s_in[cc][r][col] = v;
        }
        __syncthreads();
        for (int ci = 0; ci < 4; ci++) {
#pragma unroll
            for (int k = 0; k < 9; k++) {
                const int ky = k/3, kx = k%3;
                float wv[8];
#pragma unroll
                for (int co = 0; co < 8; co++) wv[co] = s_w[co][ci][k];
#pragma unroll
                for (int p = 0; p < 4; p++) {
                    float iv = s_in[ci][ty + 8*p + ky][tx + kx];
#pragma unroll
                    for (int co = 0; co < 8; co++) acc[p][co] += iv * wv[co];
                }
            }
        }
        __syncthreads();
    }
#pragma unroll
    for (int co = 0; co < 8; co++) {
        float bs = bias[co0+co];
#pragma unroll
        for (int p = 0; p < 4; p++) {
            float v = acc[p][co] + bs;
            if (RELU) v = (v >= 0.f) ? v : 0.1f*v;
            out[((b*COUT + co0+co)*HH + y0 + ty + 8*p)*WW + x0 + tx] = v;
        }
    }
}

__global__ void k_conv1(const float* __restrict__ wt, const float* __restrict__ bias) {
    conv3_body<49, 128, true>(g_corr, wt, bias, g_x1);
}
__global__ void k_conv2(const float* __restrict__ wt, const float* __restrict__ bias) {
    conv3_body<128, 64, true>(g_x1, wt, bias, g_x2);
}
__global__ void k_conv3k(const float* __restrict__ wt, const float* __restrict__ bias) {
    conv3_body<64, 32, true>(g_x2, wt, bias, g_x3);
}

// ---------------------------------------------------------------------------
// 5) final 5x5 conv (32->2, pad 2) + bias + flow residual -> d_out
// ---------------------------------------------------------------------------
__global__ void k_conv4(const float* __restrict__ wt, const float* __restrict__ bias,
                        float* __restrict__ out) {
    const int tx = threadIdx.x, ty = threadIdx.y;
    const int x0 = blockIdx.x*32, y0 = blockIdx.y*32;
    const int b = blockIdx.z;
    __shared__ float s_in[4][36][36];
    __shared__ float s_w[2][4][25];
    float acc[4][2];
#pragma unroll
    for (int p = 0; p < 4; p++) { acc[p][0] = 0.f; acc[p][1] = 0.f; }
    const int tid = ty*32 + tx;

    for (int c0 = 0; c0 < 32; c0 += 4) {
        if (tid < 200) {
            int co = tid/100, r = tid%100, ci = r/25, k = r%25;
            s_w[co][ci][k] = wt[(co*32 + c0+ci)*25 + k];
        }
        for (int i = tid; i < 4*36*36; i += 256) {
            int cc = i/(36*36), r = (i/36)%36, col = i%36;
            int gy = y0 + r - 2, gx = x0 + col - 2;
            float v = 0.f;
            if (gy >= 0 && gy < HH && gx >= 0 && gx < WW)
                v = g_x3[((b*32 + c0+cc)*HH + gy)*WW + gx];
            s_in[cc][r][col] = v;
        }
        __syncthreads();
        for (int ci = 0; ci < 4; ci++) {
#pragma unroll
            for (int k = 0; k < 25; k++) {
                const int ky = k/5, kx = k%5;
                float w0 = s_w[0][ci][k];
                float w1 = s_w[1][ci][k];
#pragma unroll
                for (int p = 0; p < 4; p++) {
                    float iv = s_in[ci][ty + 8*p + ky][tx + kx];
                    acc[p][0] += iv * w0;
                    acc[p][1] += iv * w1;
                }
            }
        }
        __syncthreads();
    }
#pragma unroll
    for (int co = 0; co < 2; co++) {
        float bs = bias[co];
#pragma unroll
        for (int p = 0; p < 4; p++) {
            int o = ((b*2 + co)*HH + y0 + ty + 8*p)*WW + x0 + tx;
            out[o] = g_flow[o] + bs + acc[p][co];
        }
    }
}

// ---------------------------------------------------------------------------
extern "C" void kernel_launch(void* const* d_in, const int* in_sizes, int n_in,
                              void* d_out, int out_size) {
    const float* featFirst  = (const float*)d_in[2];
    const float* featSecond = (const float*)d_in[3];
    const float* tflow      = (const float*)d_in[4];
    const float* wu         = (const float*)d_in[5];
    const float* w1 = (const float*)d_in[6];
    const float* b1 = (const float*)d_in[7];
    const float* w2 = (const float*)d_in[8];
    const float* b2 = (const float*)d_in[9];
    const float* w3 = (const float*)d_in[10];
    const float* b3 = (const float*)d_in[11];
    const float* w4 = (const float*)d_in[12];
    const float* b4 = (const float*)d_in[13];
    float* out = (float*)d_out;

    k_upflow<<<512, 1024>>>(tflow, wu);
    k_warp<<<dim3(128, 16), 128>>>(featSecond);
    k_corr<<<dim3(4, 16, 16), dim3(32, 8)>>>(featFirst);
    k_conv1 <<<dim3(4, 4, 16*16), dim3(32, 8)>>>(w1, b1);
    k_conv2 <<<dim3(4, 4, 16*8),  dim3(32, 8)>>>(w2, b2);
    k_conv3k<<<dim3(4, 4, 16*4),  dim3(32, 8)>>>(w3, b3);
    k_conv4 <<<dim3(4, 4, 16), dim3(32, 8)>>>(w4, b4, out);
}